// round 3
// baseline (speedup 1.0000x reference)
#include <cuda_runtime.h>

#define N_NODES 50000
#define N_EDGES 800000
#define C 64
#define CE 32

// ---- device scratch (no allocation allowed) ----
__device__ float g_xw[N_NODES * C];     // x @ weight_node
__device__ float g_sdst[N_NODES];       // <xw[n], wa[0:64]>
__device__ float g_ssrc[N_NODES];       // <xw[n], wa[96:160]>
__device__ float g_ev[N_EDGES];         // exp(leakyrelu(alpha))
__device__ float g_sum[N_NODES];        // segment sum of exp
__device__ int   g_src[N_EDGES];        // unpacked edge sources
__device__ int   g_dst[N_EDGES];        // unpacked edge destinations
__device__ int   g_is64;                // 1 if edge_index buffer is int64

// ---------------------------------------------------------------------------
// K-1a: detect edge_index dtype. View buffer as int32 words. For int64 data
// with values in [0, 50000), every odd word is 0. For int32 data, odd words
// are random node ids (nonzero w.p. ~1-2e-5 each).
__global__ void k_detect(const int* __restrict__ ei32) {
    __shared__ int any_nonzero;
    if (threadIdx.x == 0) any_nonzero = 0;
    __syncthreads();
    // odd words 1,3,...,511 — in-bounds for both dtypes (min buffer 1.6M words)
    int v = ei32[2 * threadIdx.x + 1];
    if (v != 0) atomicOr(&any_nonzero, 1);
    __syncthreads();
    if (threadIdx.x == 0) g_is64 = any_nonzero ? 0 : 1;
}

// K-1b: unpack src/dst to int32 with the right stride for the detected dtype.
__global__ void k_convert(const int* __restrict__ ei32) {
    int e = blockIdx.x * blockDim.x + threadIdx.x;
    if (e >= N_EDGES) return;
    if (g_is64) {
        g_src[e] = ei32[2 * e];                     // lo word of int64 src
        g_dst[e] = ei32[2 * N_EDGES + 2 * e];       // lo word of int64 dst
    } else {
        g_src[e] = ei32[e];
        g_dst[e] = ei32[N_EDGES + e];
    }
}

// ---------------------------------------------------------------------------
// K0: out = bias broadcast, segsum = 0
__global__ void k_init(const float* __restrict__ bias, float* __restrict__ out) {
    int idx = blockIdx.x * blockDim.x + threadIdx.x;
    if (idx < N_NODES * C) out[idx] = bias[idx & (C - 1)];
    if (idx < N_NODES) g_sum[idx] = 0.f;
}

// ---------------------------------------------------------------------------
// K1: xw = x @ W   (tile: 64 rows x 64 cols per 256-thread block)
__global__ void k_gemm(const float* __restrict__ x, const float* __restrict__ W) {
    __shared__ float ws[64][64];
    __shared__ float xs[64][65];
    const int tid = threadIdx.x;
    const int row0 = blockIdx.x * 64;

    for (int i = tid; i < 64 * 64; i += 256) ws[i >> 6][i & 63] = W[i];
    for (int i = tid; i < 64 * 64; i += 256) {
        int r = i >> 6, c = i & 63;
        int gr = row0 + r;
        xs[r][c] = (gr < N_NODES) ? x[(size_t)gr * 64 + c] : 0.f;
    }
    __syncthreads();

    const int r  = tid >> 2;           // 0..63
    const int c0 = (tid & 3) * 16;     // 0,16,32,48
    float4 acc[4];
    #pragma unroll
    for (int j = 0; j < 4; j++) acc[j] = make_float4(0.f, 0.f, 0.f, 0.f);

    #pragma unroll
    for (int k = 0; k < 64; k++) {
        float xv = xs[r][k];
        #pragma unroll
        for (int j = 0; j < 4; j++) {
            float4 wv = *(const float4*)&ws[k][c0 + 4 * j];
            acc[j].x += xv * wv.x;
            acc[j].y += xv * wv.y;
            acc[j].z += xv * wv.z;
            acc[j].w += xv * wv.w;
        }
    }
    int gr = row0 + r;
    if (gr < N_NODES) {
        float4* dst = (float4*)(g_xw + (size_t)gr * 64 + c0);
        #pragma unroll
        for (int j = 0; j < 4; j++) dst[j] = acc[j];
    }
}

// ---------------------------------------------------------------------------
// K2: per-node attention scores (one warp per node)
__global__ void k_scores(const float* __restrict__ wa) {
    int warp = (blockIdx.x * blockDim.x + threadIdx.x) >> 5;
    int lane = threadIdx.x & 31;
    if (warp >= N_NODES) return;
    float a = g_xw[(size_t)warp * 64 + lane];
    float b = g_xw[(size_t)warp * 64 + 32 + lane];
    float sd = a * wa[lane]      + b * wa[32 + lane];
    float ss = a * wa[96 + lane] + b * wa[128 + lane];
    #pragma unroll
    for (int o = 16; o; o >>= 1) {
        sd += __shfl_xor_sync(0xffffffffu, sd, o);
        ss += __shfl_xor_sync(0xffffffffu, ss, o);
    }
    if (lane == 0) { g_sdst[warp] = sd; g_ssrc[warp] = ss; }
}

// ---------------------------------------------------------------------------
// K3: per-edge alpha -> exp -> segment-sum atomics.  4 edges per warp,
// each 8-lane group does a float4-vectorized 32-dim dot over edge_attr.
__global__ void k_edge(const float* __restrict__ ea,
                       const float* __restrict__ wa) {
    int warp = (blockIdx.x * blockDim.x + threadIdx.x) >> 5;
    int lane = threadIdx.x & 31;
    int g = lane >> 3, q = lane & 7;
    int e = warp * 4 + g;
    if (e >= N_EDGES) return;

    float4 v = ((const float4*)(ea + (size_t)e * CE))[q];
    float4 w = ((const float4*)(wa + 64))[q];
    float p = v.x * w.x + v.y * w.y + v.z * w.z + v.w * w.w;
    p += __shfl_xor_sync(0xffffffffu, p, 4);
    p += __shfl_xor_sync(0xffffffffu, p, 2);
    p += __shfl_xor_sync(0xffffffffu, p, 1);

    if (q == 0) {
        int src = g_src[e];
        int dst = g_dst[e];
        float alpha = p + g_sdst[dst] + g_ssrc[src];
        alpha = alpha > 0.f ? alpha : 0.2f * alpha;   // leaky_relu
        float ev = expf(alpha);                        // max-shift omitted (safe range)
        g_ev[e] = ev;
        atomicAdd(&g_sum[dst], ev);
    }
}

// ---------------------------------------------------------------------------
// K4: weighted scatter:  out[dst] += (ev/sum[dst]) * xw[src]
// 2 edges per warp; each 16-lane group covers 64 channels as float4,
// accumulated with vectorized red (atomicAdd(float4*), cc >= 9.0).
__global__ void k_scatter(float* __restrict__ out) {
    int warp = (blockIdx.x * blockDim.x + threadIdx.x) >> 5;
    int lane = threadIdx.x & 31;
    int g = lane >> 4, q = lane & 15;
    int e = warp * 2 + g;
    if (e >= N_EDGES) return;

    int src = 0, dst = 0; float w = 0.f;
    if (q == 0) {
        src = g_src[e];
        dst = g_dst[e];
        w = g_ev[e] / (g_sum[dst] + 1e-16f);
    }
    int base = g << 4;
    src = __shfl_sync(0xffffffffu, src, base);
    dst = __shfl_sync(0xffffffffu, dst, base);
    w   = __shfl_sync(0xffffffffu, w,   base);

    float4 xv = ((const float4*)(g_xw + (size_t)src * 64))[q];
    float4 m = make_float4(w * xv.x, w * xv.y, w * xv.z, w * xv.w);
#if __CUDA_ARCH__ >= 900
    atomicAdd((float4*)(out + (size_t)dst * 64 + q * 4), m);
#else
    float* o = out + (size_t)dst * 64 + q * 4;
    atomicAdd(o + 0, m.x); atomicAdd(o + 1, m.y);
    atomicAdd(o + 2, m.z); atomicAdd(o + 3, m.w);
#endif
}

// ---------------------------------------------------------------------------
extern "C" void kernel_launch(void* const* d_in, const int* in_sizes, int n_in,
                              void* d_out, int out_size) {
    // Resolve inputs by element count (all six are distinct) — robust to
    // metadata ordering:
    //   x:3200000  edge_index:1600000  edge_attr:25600000
    //   weight_node:4096  weight_triplet_att:160  bias:64
    const float* x    = nullptr;
    const int*   ei32 = nullptr;    // raw edge_index words (dtype detected on device)
    const float* ea   = nullptr;
    const float* W    = nullptr;
    const float* wa   = nullptr;
    const float* bias = nullptr;
    for (int i = 0; i < n_in; i++) {
        switch (in_sizes[i]) {
            case N_NODES * C:      x    = (const float*)d_in[i]; break;
            case 2 * N_EDGES:      ei32 = (const int*)d_in[i];   break;
            case N_EDGES * CE:     ea   = (const float*)d_in[i]; break;
            case C * C:            W    = (const float*)d_in[i]; break;
            case 2 * C + CE:       wa   = (const float*)d_in[i]; break;
            case C:                bias = (const float*)d_in[i]; break;
        }
    }
    float* out = (float*)d_out;

    k_detect<<<1, 256>>>(ei32);
    k_convert<<<(N_EDGES + 255) / 256, 256>>>(ei32);
    k_init<<<(N_NODES * C + 255) / 256, 256>>>(bias, out);
    k_gemm<<<(N_NODES + 63) / 64, 256>>>(x, W);
    k_scores<<<(N_NODES + 7) / 8, 256>>>(wa);
    k_edge<<<(N_EDGES / 4 + 7) / 8, 256>>>(ea, wa);
    k_scatter<<<(N_EDGES / 2 + 7) / 8, 256>>>(out);
}

// round 5
// speedup vs baseline: 1.3742x; 1.3742x over previous
#include <cuda_runtime.h>

#define N_NODES 50000
#define N_EDGES 800000
#define C 64
#define CE 32

// ---- device scratch (no allocation allowed) ----
__device__ float g_xw[N_NODES * C];     // x @ weight_node
__device__ float g_sdst[N_NODES];       // <xw[n], wa[0:64]>
__device__ float g_ssrc[N_NODES];       // <xw[n], wa[96:160]>
__device__ float g_ev[N_EDGES];         // exp(leakyrelu(alpha))
__device__ float g_sum[N_NODES];        // segment sum of exp
__device__ int   g_src[N_EDGES];        // unpacked edge sources
__device__ int   g_dst[N_EDGES];        // unpacked edge destinations
__device__ int   g_is64;                // 1 if edge_index buffer is int64

#define FMA_F32X2(d, a, b) \
    asm("fma.rn.f32x2 %0, %1, %2, %0;" : "+l"(d) : "l"(a), "l"(b))
#define PACK_F32X2(d, lo, hi) \
    asm("mov.b64 %0, {%1, %2};" : "=l"(d) : "f"(lo), "f"(hi))

// ---------------------------------------------------------------------------
// K-1a: detect edge_index dtype (int64 vs silently-int32 from JAX).
__global__ void k_detect(const int* __restrict__ ei32) {
    __shared__ int any_nonzero;
    if (threadIdx.x == 0) any_nonzero = 0;
    __syncthreads();
    int v = ei32[2 * threadIdx.x + 1];   // odd words: int64 hi-halves == 0
    if (v != 0) atomicOr(&any_nonzero, 1);
    __syncthreads();
    if (threadIdx.x == 0) g_is64 = any_nonzero ? 0 : 1;
}

// K-1b: unpack src/dst to int32 with the right stride.
__global__ void k_convert(const int* __restrict__ ei32) {
    int e = blockIdx.x * blockDim.x + threadIdx.x;
    if (e >= N_EDGES) return;
    if (g_is64) {
        g_src[e] = ei32[2 * e];
        g_dst[e] = ei32[2 * N_EDGES + 2 * e];
    } else {
        g_src[e] = ei32[e];
        g_dst[e] = ei32[N_EDGES + e];
    }
}

// ---------------------------------------------------------------------------
// K0: out = bias broadcast, segsum = 0
__global__ void k_init(const float* __restrict__ bias, float* __restrict__ out) {
    int idx = blockIdx.x * blockDim.x + threadIdx.x;
    if (idx < N_NODES * C) out[idx] = bias[idx & (C - 1)];
    if (idx < N_NODES) g_sum[idx] = 0.f;
}

// ---------------------------------------------------------------------------
// K1: xw = x @ W  (128 rows x 64 cols per 256-thread block)
// Each thread: 4 rows x 8 cols via packed fma.rn.f32x2; per k-step only
// 3 vector LDS feed 32 MACs. Fused epilogue computes per-node attention
// scores (s_dst, s_src) via 8-lane butterflies.
// NOTE: xs_t row stride MUST be a multiple of 4 floats (16 B) because the
// mainloop does float4 loads from &xs_t[k][4*rg]. 132 = 33*4.
__global__ void k_gemm(const float* __restrict__ x, const float* __restrict__ W,
                       const float* __restrict__ wa) {
    __shared__ float ws[64][64];        // W[k][c]
    __shared__ float xs_t[64][132];     // x transposed: [k][row], 16B-aligned rows
    const int tid = threadIdx.x;
    const int row0 = blockIdx.x * 128;

    // stage W (coalesced float4)
    for (int i = tid; i < 64 * 16; i += 256)
        ((float4*)&ws[0][0])[i] = ((const float4*)W)[i];
    // stage x tile transposed
    for (int i = tid; i < 128 * 16; i += 256) {
        int r = i >> 4, c4 = i & 15;
        int gr = row0 + r;
        float4 v = (gr < N_NODES) ? ((const float4*)(x + (size_t)gr * 64))[c4]
                                  : make_float4(0.f, 0.f, 0.f, 0.f);
        xs_t[c4 * 4 + 0][r] = v.x;
        xs_t[c4 * 4 + 1][r] = v.y;
        xs_t[c4 * 4 + 2][r] = v.z;
        xs_t[c4 * 4 + 3][r] = v.w;
    }
    __syncthreads();

    const int cg = tid & 7;    // col group: cols cg*8 .. cg*8+7
    const int rg = tid >> 3;   // row group: rows rg*4 .. rg*4+3

    unsigned long long acc[4][4];
    #pragma unroll
    for (int r = 0; r < 4; r++)
        #pragma unroll
        for (int p = 0; p < 4; p++) acc[r][p] = 0ull;

    #pragma unroll 8
    for (int k = 0; k < 64; k++) {
        float4 xv = *(const float4*)&xs_t[k][rg * 4];
        ulonglong2 wA = *(const ulonglong2*)&ws[k][cg * 8];
        ulonglong2 wB = *(const ulonglong2*)&ws[k][cg * 8 + 4];
        unsigned long long xx[4];
        PACK_F32X2(xx[0], xv.x, xv.x);
        PACK_F32X2(xx[1], xv.y, xv.y);
        PACK_F32X2(xx[2], xv.z, xv.z);
        PACK_F32X2(xx[3], xv.w, xv.w);
        #pragma unroll
        for (int r = 0; r < 4; r++) {
            FMA_F32X2(acc[r][0], xx[r], wA.x);
            FMA_F32X2(acc[r][1], xx[r], wA.y);
            FMA_F32X2(acc[r][2], xx[r], wB.x);
            FMA_F32X2(acc[r][3], xx[r], wB.y);
        }
    }

    // attention weights for this thread's 8 columns
    float wad[8], was[8];
    #pragma unroll
    for (int j = 0; j < 8; j++) {
        wad[j] = wa[cg * 8 + j];
        was[j] = wa[96 + cg * 8 + j];
    }

    #pragma unroll
    for (int r = 0; r < 4; r++) {
        int row = row0 + rg * 4 + r;
        float sd = 0.f, ss = 0.f;
        float v[8];
        #pragma unroll
        for (int p = 0; p < 4; p++) {
            v[2 * p]     = __uint_as_float((unsigned)(acc[r][p] & 0xffffffffull));
            v[2 * p + 1] = __uint_as_float((unsigned)(acc[r][p] >> 32));
        }
        #pragma unroll
        for (int j = 0; j < 8; j++) {
            sd += v[j] * wad[j];
            ss += v[j] * was[j];
        }
        // reduce over the 8 col-groups (adjacent lanes, xor on low 3 bits)
        #pragma unroll
        for (int o = 4; o; o >>= 1) {
            sd += __shfl_xor_sync(0xffffffffu, sd, o);
            ss += __shfl_xor_sync(0xffffffffu, ss, o);
        }
        if (row < N_NODES) {
            ulonglong2* dst = (ulonglong2*)(g_xw + (size_t)row * 64 + cg * 8);
            dst[0] = make_ulonglong2(acc[r][0], acc[r][1]);
            dst[1] = make_ulonglong2(acc[r][2], acc[r][3]);
            if (cg == 0) { g_sdst[row] = sd; g_ssrc[row] = ss; }
        }
    }
}

// ---------------------------------------------------------------------------
// K3: per-edge alpha -> exp -> segment-sum atomics.  4 edges per warp,
// each 8-lane group does a float4-vectorized 32-dim dot over edge_attr.
__global__ void k_edge(const float* __restrict__ ea,
                       const float* __restrict__ wa) {
    int warp = (blockIdx.x * blockDim.x + threadIdx.x) >> 5;
    int lane = threadIdx.x & 31;
    int g = lane >> 3, q = lane & 7;
    int e = warp * 4 + g;
    if (e >= N_EDGES) return;

    float4 v = ((const float4*)(ea + (size_t)e * CE))[q];
    float4 w = ((const float4*)(wa + 64))[q];
    float p = v.x * w.x + v.y * w.y + v.z * w.z + v.w * w.w;
    p += __shfl_xor_sync(0xffffffffu, p, 4);
    p += __shfl_xor_sync(0xffffffffu, p, 2);
    p += __shfl_xor_sync(0xffffffffu, p, 1);

    if (q == 0) {
        int src = g_src[e];
        int dst = g_dst[e];
        float alpha = p + g_sdst[dst] + g_ssrc[src];
        alpha = alpha > 0.f ? alpha : 0.2f * alpha;   // leaky_relu
        float ev = expf(alpha);                        // max-shift omitted (safe range)
        g_ev[e] = ev;
        atomicAdd(&g_sum[dst], ev);
    }
}

// ---------------------------------------------------------------------------
// K4: weighted scatter:  out[dst] += (ev/sum[dst]) * xw[src]
// 2 edges per warp; vectorized atomicAdd(float4*).
__global__ void k_scatter(float* __restrict__ out) {
    int warp = (blockIdx.x * blockDim.x + threadIdx.x) >> 5;
    int lane = threadIdx.x & 31;
    int g = lane >> 4, q = lane & 15;
    int e = warp * 2 + g;
    if (e >= N_EDGES) return;

    int src = 0, dst = 0; float w = 0.f;
    if (q == 0) {
        src = g_src[e];
        dst = g_dst[e];
        w = g_ev[e] / (g_sum[dst] + 1e-16f);
    }
    int base = g << 4;
    src = __shfl_sync(0xffffffffu, src, base);
    dst = __shfl_sync(0xffffffffu, dst, base);
    w   = __shfl_sync(0xffffffffu, w,   base);

    float4 xv = ((const float4*)(g_xw + (size_t)src * 64))[q];
    float4 m = make_float4(w * xv.x, w * xv.y, w * xv.z, w * xv.w);
#if __CUDA_ARCH__ >= 900
    atomicAdd((float4*)(out + (size_t)dst * 64 + q * 4), m);
#else
    float* o = out + (size_t)dst * 64 + q * 4;
    atomicAdd(o + 0, m.x); atomicAdd(o + 1, m.y);
    atomicAdd(o + 2, m.z); atomicAdd(o + 3, m.w);
#endif
}

// ---------------------------------------------------------------------------
extern "C" void kernel_launch(void* const* d_in, const int* in_sizes, int n_in,
                              void* d_out, int out_size) {
    const float* x    = nullptr;
    const int*   ei32 = nullptr;
    const float* ea   = nullptr;
    const float* W    = nullptr;
    const float* wa   = nullptr;
    const float* bias = nullptr;
    for (int i = 0; i < n_in; i++) {
        switch (in_sizes[i]) {
            case N_NODES * C:      x    = (const float*)d_in[i]; break;
            case 2 * N_EDGES:      ei32 = (const int*)d_in[i];   break;
            case N_EDGES * CE:     ea   = (const float*)d_in[i]; break;
            case C * C:            W    = (const float*)d_in[i]; break;
            case 2 * C + CE:       wa   = (const float*)d_in[i]; break;
            case C:                bias = (const float*)d_in[i]; break;
        }
    }
    float* out = (float*)d_out;

    k_detect<<<1, 256>>>(ei32);
    k_convert<<<(N_EDGES + 255) / 256, 256>>>(ei32);
    k_init<<<(N_NODES * C + 255) / 256, 256>>>(bias, out);
    k_gemm<<<(N_NODES + 127) / 128, 256>>>(x, W, wa);
    k_edge<<<(N_EDGES / 4 + 7) / 8, 256>>>(ea, wa);
    k_scatter<<<(N_EDGES / 2 + 7) / 8, 256>>>(out);
}

// round 6
// speedup vs baseline: 1.5345x; 1.1166x over previous
#include <cuda_runtime.h>

#define N_NODES 50000
#define N_EDGES 800000
#define C 64
#define CE 32

// ---- device scratch (no allocation allowed) ----
__device__ float g_xw[N_NODES * C];     // x @ weight_node
__device__ float g_sdst[N_NODES];       // <xw[n], wa[0:64]>
__device__ float g_ssrc[N_NODES];       // <xw[n], wa[96:160]>
__device__ float g_sum[N_NODES];        // segment sum of exp
__device__ int   g_is64;                // 1 if edge_index buffer is int64

#define FMA_F32X2(d, a, b) \
    asm("fma.rn.f32x2 %0, %1, %2, %0;" : "+l"(d) : "l"(a), "l"(b))
#define PACK_F32X2(d, lo, hi) \
    asm("mov.b64 %0, {%1, %2};" : "=l"(d) : "f"(lo), "f"(hi))

// ---------------------------------------------------------------------------
// K-1: detect edge_index dtype (int64 vs silently-int32 from JAX).
__global__ void k_detect(const int* __restrict__ ei32) {
    __shared__ int any_nonzero;
    if (threadIdx.x == 0) any_nonzero = 0;
    __syncthreads();
    int v = ei32[2 * threadIdx.x + 1];   // odd words: int64 hi-halves == 0
    if (v != 0) atomicOr(&any_nonzero, 1);
    __syncthreads();
    if (threadIdx.x == 0) g_is64 = any_nonzero ? 0 : 1;
}

// ---------------------------------------------------------------------------
// K0: out = 0 (bias added in k_norm), segsum = 0
__global__ void k_init(float* __restrict__ out) {
    int idx = blockIdx.x * blockDim.x + threadIdx.x;
    if (idx < (N_NODES * C) / 4)
        ((float4*)out)[idx] = make_float4(0.f, 0.f, 0.f, 0.f);
    if (idx < N_NODES) g_sum[idx] = 0.f;
}

// ---------------------------------------------------------------------------
// K1: xw = x @ W  (128 rows x 64 cols per 256-thread block), fused per-node
// attention scores in the epilogue. Packed fma.rn.f32x2 mainloop.
__global__ void __launch_bounds__(256, 4)
k_gemm(const float* __restrict__ x, const float* __restrict__ W,
       const float* __restrict__ wa) {
    __shared__ float ws[64][64];        // W[k][c]
    __shared__ float xs_t[64][132];     // x transposed: [k][row], 16B-aligned rows
    const int tid = threadIdx.x;
    const int row0 = blockIdx.x * 128;

    for (int i = tid; i < 64 * 16; i += 256)
        ((float4*)&ws[0][0])[i] = ((const float4*)W)[i];
    for (int i = tid; i < 128 * 16; i += 256) {
        int r = i >> 4, c4 = i & 15;
        int gr = row0 + r;
        float4 v = (gr < N_NODES) ? ((const float4*)(x + (size_t)gr * 64))[c4]
                                  : make_float4(0.f, 0.f, 0.f, 0.f);
        xs_t[c4 * 4 + 0][r] = v.x;
        xs_t[c4 * 4 + 1][r] = v.y;
        xs_t[c4 * 4 + 2][r] = v.z;
        xs_t[c4 * 4 + 3][r] = v.w;
    }
    __syncthreads();

    const int cg = tid & 7;    // cols cg*8 .. cg*8+7
    const int rg = tid >> 3;   // rows rg*4 .. rg*4+3

    unsigned long long acc[4][4];
    #pragma unroll
    for (int r = 0; r < 4; r++)
        #pragma unroll
        for (int p = 0; p < 4; p++) acc[r][p] = 0ull;

    #pragma unroll 8
    for (int k = 0; k < 64; k++) {
        float4 xv = *(const float4*)&xs_t[k][rg * 4];
        ulonglong2 wA = *(const ulonglong2*)&ws[k][cg * 8];
        ulonglong2 wB = *(const ulonglong2*)&ws[k][cg * 8 + 4];
        unsigned long long xx[4];
        PACK_F32X2(xx[0], xv.x, xv.x);
        PACK_F32X2(xx[1], xv.y, xv.y);
        PACK_F32X2(xx[2], xv.z, xv.z);
        PACK_F32X2(xx[3], xv.w, xv.w);
        #pragma unroll
        for (int r = 0; r < 4; r++) {
            FMA_F32X2(acc[r][0], xx[r], wA.x);
            FMA_F32X2(acc[r][1], xx[r], wA.y);
            FMA_F32X2(acc[r][2], xx[r], wB.x);
            FMA_F32X2(acc[r][3], xx[r], wB.y);
        }
    }

    float wad[8], was[8];
    #pragma unroll
    for (int j = 0; j < 8; j++) {
        wad[j] = wa[cg * 8 + j];
        was[j] = wa[96 + cg * 8 + j];
    }

    #pragma unroll
    for (int r = 0; r < 4; r++) {
        int row = row0 + rg * 4 + r;
        float sd = 0.f, ss = 0.f;
        float v[8];
        #pragma unroll
        for (int p = 0; p < 4; p++) {
            v[2 * p]     = __uint_as_float((unsigned)(acc[r][p] & 0xffffffffull));
            v[2 * p + 1] = __uint_as_float((unsigned)(acc[r][p] >> 32));
        }
        #pragma unroll
        for (int j = 0; j < 8; j++) {
            sd += v[j] * wad[j];
            ss += v[j] * was[j];
        }
        #pragma unroll
        for (int o = 4; o; o >>= 1) {
            sd += __shfl_xor_sync(0xffffffffu, sd, o);
            ss += __shfl_xor_sync(0xffffffffu, ss, o);
        }
        if (row < N_NODES) {
            ulonglong2* dst = (ulonglong2*)(g_xw + (size_t)row * 64 + cg * 8);
            dst[0] = make_ulonglong2(acc[r][0], acc[r][1]);
            dst[1] = make_ulonglong2(acc[r][2], acc[r][3]);
            if (cg == 0) { g_sdst[row] = sd; g_ssrc[row] = ss; }
        }
    }
}

// ---------------------------------------------------------------------------
// K2 (FUSED): per edge, in one pass:
//   p     = <edge_attr[e], wa[64:96]>            (16 lanes x float2)
//   alpha = leakyrelu(p + sdst[dst] + ssrc[src])
//   ev    = exp(alpha);  g_sum[dst] += ev        (atomic)
//   out[dst] += ev * xw[src]                     (UNNORMALIZED; red.v4)
// Normalization by g_sum[dst] happens in k_norm (linearity of segment-sum).
__global__ void k_fused(const int* __restrict__ ei32,
                        const float* __restrict__ ea,
                        const float* __restrict__ wa,
                        float* __restrict__ out) {
    int warp = (blockIdx.x * blockDim.x + threadIdx.x) >> 5;
    int lane = threadIdx.x & 31;
    int g = lane >> 4, q = lane & 15;
    int e = warp * 2 + g;
    if (e >= N_EDGES) return;

    // 32-dim edge_attr dot: 16 lanes x float2 (warp covers 256B contiguous)
    float2 v = ((const float2*)(ea + (size_t)e * CE))[q];
    float2 w = ((const float2*)(wa + 64))[q];
    float p = v.x * w.x + v.y * w.y;
    #pragma unroll
    for (int o = 8; o; o >>= 1)
        p += __shfl_xor_sync(0xffffffffu, p, o);

    int src = 0, dst = 0; float ev = 0.f;
    if (q == 0) {
        if (g_is64) {
            src = ei32[2 * e];
            dst = ei32[2 * N_EDGES + 2 * e];
        } else {
            src = ei32[e];
            dst = ei32[N_EDGES + e];
        }
        float alpha = p + g_sdst[dst] + g_ssrc[src];
        alpha = alpha > 0.f ? alpha : 0.2f * alpha;   // leaky_relu
        ev = __expf(alpha);                            // max-shift safe to omit
        atomicAdd(&g_sum[dst], ev);
    }
    int base = g << 4;
    src = __shfl_sync(0xffffffffu, src, base);
    dst = __shfl_sync(0xffffffffu, dst, base);
    ev  = __shfl_sync(0xffffffffu, ev,  base);

    float4 xv = ((const float4*)(g_xw + (size_t)src * 64))[q];
    float4 m = make_float4(ev * xv.x, ev * xv.y, ev * xv.z, ev * xv.w);
#if __CUDA_ARCH__ >= 900
    atomicAdd((float4*)(out + (size_t)dst * 64 + q * 4), m);
#else
    float* o = out + (size_t)dst * 64 + q * 4;
    atomicAdd(o + 0, m.x); atomicAdd(o + 1, m.y);
    atomicAdd(o + 2, m.z); atomicAdd(o + 3, m.w);
#endif
}

// ---------------------------------------------------------------------------
// K3: out = out / (sum[dst] + eps) + bias   (float4 over 50000*16 vectors)
__global__ void k_norm(float* __restrict__ out, const float* __restrict__ bias) {
    int idx = blockIdx.x * blockDim.x + threadIdx.x;
    if (idx >= (N_NODES * C) / 4) return;
    int n  = idx >> 4;          // node
    int c4 = idx & 15;          // float4 slot within node
    float inv = 1.0f / (g_sum[n] + 1e-16f);
    float4 o = ((float4*)out)[idx];
    float4 b = ((const float4*)bias)[c4];
    o.x = o.x * inv + b.x;
    o.y = o.y * inv + b.y;
    o.z = o.z * inv + b.z;
    o.w = o.w * inv + b.w;
    ((float4*)out)[idx] = o;
}

// ---------------------------------------------------------------------------
extern "C" void kernel_launch(void* const* d_in, const int* in_sizes, int n_in,
                              void* d_out, int out_size) {
    const float* x    = nullptr;
    const int*   ei32 = nullptr;
    const float* ea   = nullptr;
    const float* W    = nullptr;
    const float* wa   = nullptr;
    const float* bias = nullptr;
    for (int i = 0; i < n_in; i++) {
        switch (in_sizes[i]) {
            case N_NODES * C:      x    = (const float*)d_in[i]; break;
            case 2 * N_EDGES:      ei32 = (const int*)d_in[i];   break;
            case N_EDGES * CE:     ea   = (const float*)d_in[i]; break;
            case C * C:            W    = (const float*)d_in[i]; break;
            case 2 * C + CE:       wa   = (const float*)d_in[i]; break;
            case C:                bias = (const float*)d_in[i]; break;
        }
    }
    float* out = (float*)d_out;

    k_detect<<<1, 256>>>(ei32);
    k_init<<<(N_NODES * C / 4 + 255) / 256, 256>>>(out);
    k_gemm<<<(N_NODES + 127) / 128, 256>>>(x, W, wa);
    k_fused<<<(N_EDGES / 2 + 7) / 8, 256>>>(ei32, ea, wa, out);
    k_norm<<<(N_NODES * C / 4 + 255) / 256, 256>>>(out, bias);
}

// round 7
// speedup vs baseline: 2.0840x; 1.3581x over previous
#include <cuda_runtime.h>

#define N_NODES 50000
#define N_EDGES 800000
#define C 64
#define CE 32

// ---- device scratch (no allocation allowed) ----
__device__ float g_xw[N_NODES * C];     // x @ weight_node
__device__ float g_sdst[N_NODES];       // <xw[n], wa[0:64]>
__device__ float g_ssrc[N_NODES];       // <xw[n], wa[96:160]>
__device__ float g_sum[N_NODES];        // segment sum of exp
__device__ int   g_is64;                // 1 if edge_index buffer is int64

#define FMA_F32X2(d, a, b) \
    asm("fma.rn.f32x2 %0, %1, %2, %0;" : "+l"(d) : "l"(a), "l"(b))
#define PACK_F32X2(d, lo, hi) \
    asm("mov.b64 %0, {%1, %2};" : "=l"(d) : "f"(lo), "f"(hi))

// ---------------------------------------------------------------------------
// K-1: detect edge_index dtype (int64 vs silently-int32 from JAX).
__global__ void k_detect(const int* __restrict__ ei32) {
    __shared__ int any_nonzero;
    if (threadIdx.x == 0) any_nonzero = 0;
    __syncthreads();
    int v = ei32[2 * threadIdx.x + 1];   // odd words: int64 hi-halves == 0
    if (v != 0) atomicOr(&any_nonzero, 1);
    __syncthreads();
    if (threadIdx.x == 0) g_is64 = any_nonzero ? 0 : 1;
}

// ---------------------------------------------------------------------------
// K0: out = 0 (bias added in k_norm), segsum = 0
__global__ void k_init(float* __restrict__ out) {
    int idx = blockIdx.x * blockDim.x + threadIdx.x;
    if (idx < (N_NODES * C) / 4)
        ((float4*)out)[idx] = make_float4(0.f, 0.f, 0.f, 0.f);
    if (idx < N_NODES) g_sum[idx] = 0.f;
}

// ---------------------------------------------------------------------------
// K1: xw = x @ W  (128 rows x 64 cols per 256-thread block), fused per-node
// attention scores in the epilogue. Packed fma.rn.f32x2 mainloop.
__global__ void __launch_bounds__(256, 4)
k_gemm(const float* __restrict__ x, const float* __restrict__ W,
       const float* __restrict__ wa) {
    __shared__ float ws[64][64];        // W[k][c]
    __shared__ float xs_t[64][132];     // x transposed: [k][row], 16B-aligned rows
    const int tid = threadIdx.x;
    const int row0 = blockIdx.x * 128;

    for (int i = tid; i < 64 * 16; i += 256)
        ((float4*)&ws[0][0])[i] = ((const float4*)W)[i];
    for (int i = tid; i < 128 * 16; i += 256) {
        int r = i >> 4, c4 = i & 15;
        int gr = row0 + r;
        float4 v = (gr < N_NODES) ? ((const float4*)(x + (size_t)gr * 64))[c4]
                                  : make_float4(0.f, 0.f, 0.f, 0.f);
        xs_t[c4 * 4 + 0][r] = v.x;
        xs_t[c4 * 4 + 1][r] = v.y;
        xs_t[c4 * 4 + 2][r] = v.z;
        xs_t[c4 * 4 + 3][r] = v.w;
    }
    __syncthreads();

    const int cg = tid & 7;    // cols cg*8 .. cg*8+7
    const int rg = tid >> 3;   // rows rg*4 .. rg*4+3

    unsigned long long acc[4][4];
    #pragma unroll
    for (int r = 0; r < 4; r++)
        #pragma unroll
        for (int p = 0; p < 4; p++) acc[r][p] = 0ull;

    #pragma unroll 8
    for (int k = 0; k < 64; k++) {
        float4 xv = *(const float4*)&xs_t[k][rg * 4];
        ulonglong2 wA = *(const ulonglong2*)&ws[k][cg * 8];
        ulonglong2 wB = *(const ulonglong2*)&ws[k][cg * 8 + 4];
        unsigned long long xx[4];
        PACK_F32X2(xx[0], xv.x, xv.x);
        PACK_F32X2(xx[1], xv.y, xv.y);
        PACK_F32X2(xx[2], xv.z, xv.z);
        PACK_F32X2(xx[3], xv.w, xv.w);
        #pragma unroll
        for (int r = 0; r < 4; r++) {
            FMA_F32X2(acc[r][0], xx[r], wA.x);
            FMA_F32X2(acc[r][1], xx[r], wA.y);
            FMA_F32X2(acc[r][2], xx[r], wB.x);
            FMA_F32X2(acc[r][3], xx[r], wB.y);
        }
    }

    float wad[8], was[8];
    #pragma unroll
    for (int j = 0; j < 8; j++) {
        wad[j] = wa[cg * 8 + j];
        was[j] = wa[96 + cg * 8 + j];
    }

    #pragma unroll
    for (int r = 0; r < 4; r++) {
        int row = row0 + rg * 4 + r;
        float sd = 0.f, ss = 0.f;
        float v[8];
        #pragma unroll
        for (int p = 0; p < 4; p++) {
            v[2 * p]     = __uint_as_float((unsigned)(acc[r][p] & 0xffffffffull));
            v[2 * p + 1] = __uint_as_float((unsigned)(acc[r][p] >> 32));
        }
        #pragma unroll
        for (int j = 0; j < 8; j++) {
            sd += v[j] * wad[j];
            ss += v[j] * was[j];
        }
        #pragma unroll
        for (int o = 4; o; o >>= 1) {
            sd += __shfl_xor_sync(0xffffffffu, sd, o);
            ss += __shfl_xor_sync(0xffffffffu, ss, o);
        }
        if (row < N_NODES) {
            ulonglong2* dst = (ulonglong2*)(g_xw + (size_t)row * 64 + cg * 8);
            dst[0] = make_ulonglong2(acc[r][0], acc[r][1]);
            dst[1] = make_ulonglong2(acc[r][2], acc[r][3]);
            if (cg == 0) { g_sdst[row] = sd; g_ssrc[row] = ss; }
        }
    }
}

// ---------------------------------------------------------------------------
// K2 (FUSED): 4 edges per warp, 8 lanes per edge.
//   p     = <edge_attr[e], wa[64:96]>   (8 lanes x float4, 3-step butterfly)
//   every lane: loads src/dst (same-addr broadcast), computes ev locally
//   lane q==0:  g_sum[dst] += ev  (RED)
//   all lanes:  out[dst*64 + q*4 + 32h] += ev * xw[src][...], h=0,1  (red.v4)
// Normalization happens in k_norm (linearity of segment-sum).
__global__ void k_fused(const int* __restrict__ ei32,
                        const float* __restrict__ ea,
                        const float* __restrict__ wa,
                        float* __restrict__ out) {
    int warp = (blockIdx.x * blockDim.x + threadIdx.x) >> 5;
    int lane = threadIdx.x & 31;
    int g = lane >> 3, q = lane & 7;
    int e = warp * 4 + g;
    if (e >= N_EDGES) return;

    // 32-dim edge_attr dot: 8 lanes x float4
    float4 v = __ldg(((const float4*)(ea + (size_t)e * CE)) + q);
    float4 w = __ldg(((const float4*)(wa + 64)) + q);
    float p = v.x * w.x + v.y * w.y + v.z * w.z + v.w * w.w;
    p += __shfl_xor_sync(0xffffffffu, p, 4);
    p += __shfl_xor_sync(0xffffffffu, p, 2);
    p += __shfl_xor_sync(0xffffffffu, p, 1);
    // all 8 lanes of the group now hold the full dot

    int src, dst;
    if (g_is64) {
        src = __ldg(ei32 + 2 * e);
        dst = __ldg(ei32 + 2 * N_EDGES + 2 * e);
    } else {
        src = __ldg(ei32 + e);
        dst = __ldg(ei32 + N_EDGES + e);
    }
    float alpha = p + __ldg(g_sdst + dst) + __ldg(g_ssrc + src);
    alpha = alpha > 0.f ? alpha : 0.2f * alpha;   // leaky_relu
    float ev = __expf(alpha);                      // max-shift safe to omit
    if (q == 0) atomicAdd(&g_sum[dst], ev);        // RED (result unused)

    const float4* xrow = (const float4*)(g_xw + (size_t)src * 64);
    float4*       orow = (float4*)(out + (size_t)dst * 64);
    #pragma unroll
    for (int h = 0; h < 2; h++) {
        float4 xv = __ldg(xrow + q + 8 * h);
        float4 m = make_float4(ev * xv.x, ev * xv.y, ev * xv.z, ev * xv.w);
#if __CUDA_ARCH__ >= 900
        atomicAdd(orow + q + 8 * h, m);
#else
        float* o = (float*)(orow + q + 8 * h);
        atomicAdd(o + 0, m.x); atomicAdd(o + 1, m.y);
        atomicAdd(o + 2, m.z); atomicAdd(o + 3, m.w);
#endif
    }
}

// ---------------------------------------------------------------------------
// K3: out = out / (sum[dst] + eps) + bias   (float4 over 50000*16 vectors)
__global__ void k_norm(float* __restrict__ out, const float* __restrict__ bias) {
    int idx = blockIdx.x * blockDim.x + threadIdx.x;
    if (idx >= (N_NODES * C) / 4) return;
    int n  = idx >> 4;          // node
    int c4 = idx & 15;          // float4 slot within node
    float inv = 1.0f / (g_sum[n] + 1e-16f);
    float4 o = ((float4*)out)[idx];
    float4 b = ((const float4*)bias)[c4];
    o.x = o.x * inv + b.x;
    o.y = o.y * inv + b.y;
    o.z = o.z * inv + b.z;
    o.w = o.w * inv + b.w;
    ((float4*)out)[idx] = o;
}

// ---------------------------------------------------------------------------
extern "C" void kernel_launch(void* const* d_in, const int* in_sizes, int n_in,
                              void* d_out, int out_size) {
    const float* x    = nullptr;
    const int*   ei32 = nullptr;
    const float* ea   = nullptr;
    const float* W    = nullptr;
    const float* wa   = nullptr;
    const float* bias = nullptr;
    for (int i = 0; i < n_in; i++) {
        switch (in_sizes[i]) {
            case N_NODES * C:      x    = (const float*)d_in[i]; break;
            case 2 * N_EDGES:      ei32 = (const int*)d_in[i];   break;
            case N_EDGES * CE:     ea   = (const float*)d_in[i]; break;
            case C * C:            W    = (const float*)d_in[i]; break;
            case 2 * C + CE:       wa   = (const float*)d_in[i]; break;
            case C:                bias = (const float*)d_in[i]; break;
        }
    }
    float* out = (float*)d_out;

    k_detect<<<1, 256>>>(ei32);
    k_init<<<(N_NODES * C / 4 + 255) / 256, 256>>>(out);
    k_gemm<<<(N_NODES + 127) / 128, 256>>>(x, W, wa);
    k_fused<<<(N_EDGES / 4 + 7) / 8, 256>>>(ei32, ea, wa, out);
    k_norm<<<(N_NODES * C / 4 + 255) / 256, 256>>>(out, bias);
}